// round 7
// baseline (speedup 1.0000x reference)
#include <cuda_runtime.h>
#include <cuda_fp16.h>

// B=8192, T=16, M=16, V=256 fixed.
#define INS_DEL 10.0f
#define FIRST_CHAR_COST 10.0f

#define WARPS_PER_BLOCK 4
#define THREADS_PER_BLOCK (WARPS_PER_BLOCK * 32)

#define K10 4.5399929762484854e-05f          // e^{-10}

// Per-warp shared: only S[t][m] = exp(-sub), fp32, row stride 18 + pad.
#define SSTRIDE 18
#define WARP_S_FLOATS 296                    // 288 + 8 pad

__device__ __forceinline__ void mma16816(float d[4],
                                         unsigned a0, unsigned a1,
                                         unsigned a2, unsigned a3,
                                         unsigned b0, unsigned b1) {
    asm volatile("mma.sync.aligned.m16n8k16.row.col.f32.f16.f16.f32 "
                 "{%0,%1,%2,%3}, {%4,%5,%6,%7}, {%8,%9}, {%0,%1,%2,%3};\n"
                 : "+f"(d[0]), "+f"(d[1]), "+f"(d[2]), "+f"(d[3])
                 : "r"(a0), "r"(a1), "r"(a2), "r"(a3), "r"(b0), "r"(b1));
}

__device__ __forceinline__ unsigned pack_h2(float x, float y) {
    __half2 h = __floats2half2_rn(x, y);
    return *(unsigned*)&h;
}

__global__ void __launch_bounds__(THREADS_PER_BLOCK, 8)
rhyme_dp_kernel(const float* __restrict__ logits,
                const int* __restrict__ tgt,
                const float* __restrict__ phon,
                float* __restrict__ out, int B)
{
    __shared__ float sS[WARPS_PER_BLOCK][WARP_S_FLOATS];

    const int w    = threadIdx.x >> 5;
    const int lane = threadIdx.x & 31;
    const int b    = blockIdx.x * WARPS_PER_BLOCK + w;
    if (b >= B) return;

    float* S = sS[w];
    const float* lg = logits + (size_t)b * (16 * 256);

    const int m   = lane & 15;    // DP column / target index
    const int g   = lane >> 2;    // MMA group id (row / n)
    const int tig = lane & 3;     // thread-in-group (k / col pairs)

    const int gm = tgt[b * 16 + m];
    const int g0 = __shfl_sync(0xffffffffu, gm, 0);

    // ---- Fused exp+GEMM: [sub_raw | Z] = exp(logits) @ [C_gather | ones] ---
    // A fragments are built straight from global logits in mma layout:
    // lane (g,tig) covers rows {g, g+8}, cols {2tig,2tig+1, +8,+9} per k-tile.
    float d0[4] = {0.f, 0.f, 0.f, 0.f};
    float d1[4] = {0.f, 0.f, 0.f, 0.f};
    float d2[4] = {0.f, 0.f, 0.f, 0.f};
    float z0_lane0;
    {
        const float* ar0 = lg + g * 256 + tig * 2;            // A row g
        const float* ar1 = lg + (g + 8) * 256 + tig * 2;      // A row g+8

        const int gn0 = __shfl_sync(0xffffffffu, gm, g);      // B col n=g
        const int gn1 = __shfl_sync(0xffffffffu, gm, 8 + g);  // B col n=g+8
        const float* br0 = phon + (size_t)gn0 * 256 + tig * 2;
        const float* br1 = phon + (size_t)gn1 * 256 + tig * 2;

        // ones-column (n=0) B fragment -> Z in d2 col 0
        const unsigned bone = (lane < 4) ? pack_h2(1.0f, 1.0f) : 0u;

#pragma unroll
        for (int kt = 0; kt < 16; ++kt) {
            const int o = kt * 16;
            float2 fa0 = *(const float2*)(ar0 + o);
            float2 fa1 = *(const float2*)(ar1 + o);
            float2 fa2 = *(const float2*)(ar0 + o + 8);
            float2 fa3 = *(const float2*)(ar1 + o + 8);
            float2 fb0 = __ldg((const float2*)(br0 + o));
            float2 fb1 = __ldg((const float2*)(br0 + o + 8));
            float2 fb2 = __ldg((const float2*)(br1 + o));
            float2 fb3 = __ldg((const float2*)(br1 + o + 8));

            unsigned a0 = pack_h2(__expf(fa0.x), __expf(fa0.y));
            unsigned a1 = pack_h2(__expf(fa1.x), __expf(fa1.y));
            unsigned a2 = pack_h2(__expf(fa2.x), __expf(fa2.y));
            unsigned a3 = pack_h2(__expf(fa3.x), __expf(fa3.y));

            mma16816(d0, a0, a1, a2, a3,
                     pack_h2(fb0.x, fb0.y), pack_h2(fb1.x, fb1.y));
            mma16816(d1, a0, a1, a2, a3,
                     pack_h2(fb2.x, fb2.y), pack_h2(fb3.x, fb3.y));
            mma16816(d2, a0, a1, a2, a3, bone, bone);
        }

        // ---- writeback: S[t][m] = exp(-sub[t][m]) --------------------------
        const float zlo = __shfl_sync(0xffffffffu, d2[0], lane & ~3);
        const float zhi = __shfl_sync(0xffffffffu, d2[2], lane & ~3);
        z0_lane0 = __shfl_sync(0xffffffffu, d2[0], 0);   // Z[0]
        const float rzlo = -__fdividef(1.0f, zlo);
        const float rzhi = -__fdividef(1.0f, zhi);

        const int mc = tig * 2;
        *(float2*)(S + g * SSTRIDE + mc) =
            make_float2(__expf(d0[0] * rzlo), __expf(d0[1] * rzlo));
        *(float2*)(S + (g + 8) * SSTRIDE + mc) =
            make_float2(__expf(d0[2] * rzhi), __expf(d0[3] * rzhi));
        *(float2*)(S + g * SSTRIDE + mc + 8) =
            make_float2(__expf(d1[0] * rzlo), __expf(d1[1] * rzlo));
        *(float2*)(S + (g + 8) * SSTRIDE + mc + 8) =
            make_float2(__expf(d1[2] * rzhi), __expf(d1[3] * rzhi));
    }
    __syncwarp();

    // ---- soft-DP wavefront in w-domain (w = exp(-dp)) ----------------------
    // w(i,j) = e^-10 * (w_up + w_left) + w_diag * exp(-sub[i-1][j-1])
    const float em1 = __expf(-10.0f * (float)(m + 1));   // w(0, m+1)
    const float em  = __expf(-10.0f * (float)m);         // w(0, m)
    float bl = K10;    // lane-0 running e^{-10*i}
    float bd = 1.0f;   // lane-0 running e^{-10*(i-1)}

    float cur = 0.0f, prev = 0.0f;
#pragma unroll
    for (int s = 0; s <= 30; ++s) {
        float leftv = __shfl_up_sync(0xffffffffu, cur, 1);
        float diagv = __shfl_up_sync(0xffffffffu, prev, 1);
        const int i = s - m + 1;
        const bool active = (i >= 1) && (i <= 16);

        float up = cur;
        if (i == 1) { up = em1; diagv = em; }
        if (m == 0) { leftv = bl; diagv = bd; }

        const int si = active ? (s - m) : 0;
        const float es = S[si * SSTRIDE + m];

        const float val = K10 * (up + leftv) + diagv * es;

        if (active) { prev = cur; cur = val; }
        bd = bl; bl *= K10;
    }

    // ---- final log + first-char term + output ------------------------------
    if (lane == 15) {
        const float fm = __expf(lg[g0]) * __fdividef(1.0f, z0_lane0);
        out[b] = -__logf(cur) + FIRST_CHAR_COST * (1.0f - fm);
    }
}

extern "C" void kernel_launch(void* const* d_in, const int* in_sizes, int n_in,
                              void* d_out, int out_size)
{
    const float* logits = (const float*)d_in[0];   // tail_logits (B,T,V) f32
    const int*   tgt    = (const int*)  d_in[1];   // target_idx  (B,M) i32
    const float* phon   = (const float*)d_in[2];   // phon_cost   (V,V) f32
    float* out = (float*)d_out;
    const int B = out_size;                        // 8192

    const int grid = (B + WARPS_PER_BLOCK - 1) / WARPS_PER_BLOCK;
    rhyme_dp_kernel<<<grid, THREADS_PER_BLOCK>>>(logits, tgt, phon, out, B);
}